// round 12
// baseline (speedup 1.0000x reference)
#include <cuda_runtime.h>

// frames: [4, B=8, C=64, H=160, W=160] fp32 ; out: [B, 256, H, W] fp32
// out_i[c,p] = sum_j exp(v_i[c,p]*v_j[c,p]) * v_j[c,p] / Z_i(p)
// Z_i(p) = sum_{j,c} exp(v_i[c,p]*v_j[c,p]);  symmetric in (i,j): 10 pairs.

#define HW_    25600   // 160*160
#define C_     64
#define B_     8
#define PX     32      // pixels per tile
#define NT     4       // consecutive tiles per block, rolling 2-buffer pipeline
#define NTHR   256
#define NROW   256     // 4 frames * 64 channels
#define TILE_F (NROW * PX)   // 32 KB

__device__ __forceinline__ float ex2f(float x) {
    float y;
    asm("ex2.approx.ftz.f32 %0, %1;" : "=f"(y) : "f"(x));
    return y;
}

__device__ __forceinline__ float rcpf(float x) {
    float y;
    asm("rcp.approx.ftz.f32 %0, %1;" : "=f"(y) : "f"(x));
    return y;
}

__device__ __forceinline__ unsigned smem_u32(const void* p) {
    unsigned a;
    asm("{ .reg .u64 t; cvta.to.shared.u64 t, %1; cvt.u32.u64 %0, t; }"
        : "=r"(a) : "l"(p));
    return a;
}

__global__ __launch_bounds__(NTHR, 3)
void frame_attn_kernel(const float* __restrict__ frames, float* __restrict__ out)
{
    __shared__ float sbuf[2][TILE_F];   // 2 rolling input buffers
    __shared__ float szp[8][4][PX];     // per-slice partial Z
    __shared__ float srz[4][PX];        // reciprocal Z per (head, px)

    const int tid   = threadIdx.x;
    const int slice = tid >> 5;          // warp id 0..7 (8 channels each)
    const int px    = tid & 31;
    const int r0    = tid >> 3;          // load-row base (0..31)
    const int c4b   = (tid & 7) * 16;    // byte offset within 128B row chunk

    const int tile0 = blockIdx.x * NT;          // 800 tiles per b, NT divides 800
    const int b     = tile0 / (HW_ / PX);       // same b for all NT tiles
    const int p0b   = (tile0 % (HW_ / PX)) * PX;

    // ---- async prefetch of one 32KB tile into sbuf[bufi] ----
    auto prefetch = [&](int p0, int bufi) {
        const char* gbase = (const char*)frames
                          + (size_t)4 * p0 + (size_t)b * C_ * HW_ * 4 + c4b;
        const unsigned sb = smem_u32(&sbuf[bufi][0]) + (unsigned)(r0 * (PX * 4) + c4b);
        #pragma unroll
        for (int it = 0; it < 8; ++it) {
            const int row = it * 32 + r0;        // 0..255 = j*64 + c
            const int j = row >> 6, c = row & 63;
            const char* g = gbase + ((size_t)j * (B_ * C_) + c) * (HW_ * 4);
            const unsigned s = sb + (unsigned)(it * 32 * PX * 4);
            asm volatile("cp.async.cg.shared.global [%0], [%1], 16;"
                         :: "r"(s), "l"(g) : "memory");
        }
        asm volatile("cp.async.commit_group;" ::: "memory");
    };

    // ---- compute + normalize + store; optionally issue next-next prefetch ----
    // pf_p0 >= 0: after the last smem read of sbuf[bufi] (post-srz barrier),
    // prefetch tile at pf_p0 into the SAME buffer (safe: all reads done).
    auto process = [&](int p0, int bufi, int pf_p0) {
        const float* svb = &sbuf[bufi][0] + (slice * 8) * PX + px;
        const float LOG2E = 1.4426950408889634f;

        float n[4][8];    // numerators stay in registers
        float zp[10];
        #pragma unroll
        for (int p = 0; p < 10; ++p) zp[p] = 0.0f;

        #pragma unroll
        for (int k = 0; k < 8; ++k) {
            float vk[4], wk[4];
            #pragma unroll
            for (int j = 0; j < 4; ++j) {
                float x = svb[(j * C_ + k) * PX];
                vk[j] = x;
                wk[j] = x * LOG2E;
            }
            {   // diagonal pairs
                float e0 = ex2f(wk[0] * vk[0]); zp[0] += e0; n[0][k] = e0 * vk[0];
                float e1 = ex2f(wk[1] * vk[1]); zp[4] += e1; n[1][k] = e1 * vk[1];
                float e2 = ex2f(wk[2] * vk[2]); zp[7] += e2; n[2][k] = e2 * vk[2];
                float e3 = ex2f(wk[3] * vk[3]); zp[9] += e3; n[3][k] = e3 * vk[3];
            }
            {   // symmetric off-diagonal pairs
                float e;
                e = ex2f(wk[0] * vk[1]); zp[1] += e; n[0][k] += e * vk[1]; n[1][k] += e * vk[0];
                e = ex2f(wk[0] * vk[2]); zp[2] += e; n[0][k] += e * vk[2]; n[2][k] += e * vk[0];
                e = ex2f(wk[0] * vk[3]); zp[3] += e; n[0][k] += e * vk[3]; n[3][k] += e * vk[0];
                e = ex2f(wk[1] * vk[2]); zp[5] += e; n[1][k] += e * vk[2]; n[2][k] += e * vk[1];
                e = ex2f(wk[1] * vk[3]); zp[6] += e; n[1][k] += e * vk[3]; n[3][k] += e * vk[1];
                e = ex2f(wk[2] * vk[3]); zp[8] += e; n[2][k] += e * vk[3]; n[3][k] += e * vk[2];
            }
        }

        // pairs: (0,0)=0 (0,1)=1 (0,2)=2 (0,3)=3 (1,1)=4 (1,2)=5 (1,3)=6 (2,2)=7 (2,3)=8 (3,3)=9
        szp[slice][0][px] = zp[0] + zp[1] + zp[2] + zp[3];
        szp[slice][1][px] = zp[1] + zp[4] + zp[5] + zp[6];
        szp[slice][2][px] = zp[2] + zp[5] + zp[7] + zp[8];
        szp[slice][3][px] = zp[3] + zp[6] + zp[8] + zp[9];
        __syncthreads();

        if (slice < 4) {
            float s = 0.0f;
            #pragma unroll
            for (int s8 = 0; s8 < 8; ++s8) s += szp[s8][slice][px];
            srz[slice][px] = rcpf(s);
        }
        __syncthreads();
        // all smem reads of sbuf[bufi] are complete -> safe to refill it
        if (pf_p0 >= 0) prefetch(pf_p0, bufi);

        // coalesced streaming stores: warp = fixed row, 32 consecutive px
        float* ob = out + ((size_t)b * 4 * C_ + slice * 8) * HW_ + p0 + px;
        #pragma unroll
        for (int i = 0; i < 4; ++i) {
            const float r = srz[i][px];
            #pragma unroll
            for (int k = 0; k < 8; ++k)
                __stcs(ob + ((size_t)i * C_ + k) * HW_, n[i][k] * r);
        }
    };

    // ---- rolling pipeline over NT tiles ----
    prefetch(p0b, 0);
    prefetch(p0b + PX, 1);

    #pragma unroll
    for (int m = 0; m < NT; ++m) {
        // wait for tile m's data (keep at most the next tile's group in flight)
        if (m < NT - 1) asm volatile("cp.async.wait_group 1;" ::: "memory");
        else            asm volatile("cp.async.wait_group 0;" ::: "memory");
        __syncthreads();   // data visible; also fences prior tile's srz reads
        process(p0b + m * PX, m & 1,
                (m + 2 < NT) ? (p0b + (m + 2) * PX) : -1);
    }
}

extern "C" void kernel_launch(void* const* d_in, const int* in_sizes, int n_in,
                              void* d_out, int out_size)
{
    const float* frames = (const float*)d_in[0];
    float* out = (float*)d_out;
    frame_attn_kernel<<<B_ * (HW_ / PX) / NT, NTHR>>>(frames, out);   // 1600
}

// round 14
// speedup vs baseline: 1.0252x; 1.0252x over previous
#include <cuda_runtime.h>

// frames: [4, B=8, C=64, H=160, W=160] fp32 ; out: [B, 256, H, W] fp32
// out_i[c,p] = sum_j exp(v_i[c,p]*v_j[c,p]) * v_j[c,p] / Z_i(p)
// Z_i(p) = sum_{j,c} exp(v_i[c,p]*v_j[c,p]);  symmetric in (i,j): 10 pairs.

#define HW_    25600   // 160*160
#define C_     64
#define B_     8
#define PX     32      // pixels per tile
#define NT     2       // consecutive tiles per block (cp.async pipelined)
#define NTHR   256
#define NROW   256     // 4 frames * 64 channels
#define TILE_F (NROW * PX)   // 32 KB

__device__ __forceinline__ float ex2f(float x) {
    float y;
    asm("ex2.approx.ftz.f32 %0, %1;" : "=f"(y) : "f"(x));
    return y;
}

__device__ __forceinline__ float rcpf(float x) {
    float y;
    asm("rcp.approx.ftz.f32 %0, %1;" : "=f"(y) : "f"(x));
    return y;
}

__device__ __forceinline__ unsigned smem_u32(const void* p) {
    unsigned a;
    asm("{ .reg .u64 t; cvta.to.shared.u64 t, %1; cvt.u32.u64 %0, t; }"
        : "=r"(a) : "l"(p));
    return a;
}

__global__ __launch_bounds__(NTHR, 3)
void frame_attn_kernel(const float* __restrict__ frames, float* __restrict__ out)
{
    __shared__ float sbuf[2][TILE_F];   // double-buffered input tiles
    __shared__ float szp[8][4][PX];     // per-slice partial Z
    __shared__ float srz[4][PX];        // reciprocal Z per (head, px)

    const int tid   = threadIdx.x;
    const int slice = tid >> 5;          // warp id 0..7 (8 channels each)
    const int px    = tid & 31;
    const int r0    = tid >> 3;          // load-row base (0..31)
    const int c4b   = (tid & 7) * 16;    // byte offset within 128B row chunk

    const int tile0 = blockIdx.x * NT;          // 800 tiles per b, NT=2 divides
    const int b     = tile0 / (HW_ / PX);       // same b for both tiles
    const int p0b   = (tile0 % (HW_ / PX)) * PX;

    // ---- async prefetch of one 32KB tile into sbuf[bufi] ----
    auto prefetch = [&](int p0, int bufi) {
        const char* gbase = (const char*)frames
                          + (size_t)4 * p0 + (size_t)b * C_ * HW_ * 4 + c4b;
        const unsigned sb = smem_u32(&sbuf[bufi][0]) + (unsigned)(r0 * (PX * 4) + c4b);
        #pragma unroll
        for (int it = 0; it < 8; ++it) {
            const int row = it * 32 + r0;        // 0..255 = j*64 + c
            const int j = row >> 6, c = row & 63;
            const char* g = gbase + ((size_t)j * (B_ * C_) + c) * (HW_ * 4);
            const unsigned s = sb + (unsigned)(it * 32 * PX * 4);
            asm volatile("cp.async.cg.shared.global [%0], [%1], 16;"
                         :: "r"(s), "l"(g) : "memory");
        }
        asm volatile("cp.async.commit_group;" ::: "memory");
    };

    // ---- compute + normalize + store for the tile in sbuf[bufi] ----
    auto process = [&](int p0, int bufi) {
        const float* svb = &sbuf[bufi][0] + (slice * 8) * PX + px;
        const float LOG2E = 1.4426950408889634f;

        float n[4][8];    // numerators stay in registers
        float zp[10];
        #pragma unroll
        for (int p = 0; p < 10; ++p) zp[p] = 0.0f;

        #pragma unroll
        for (int k = 0; k < 8; ++k) {
            float vk[4], wk[4];
            #pragma unroll
            for (int j = 0; j < 4; ++j) {
                float x = svb[(j * C_ + k) * PX];
                vk[j] = x;
                wk[j] = x * LOG2E;
            }
            {   // diagonal pairs
                float e0 = ex2f(wk[0] * vk[0]); zp[0] += e0; n[0][k] = e0 * vk[0];
                float e1 = ex2f(wk[1] * vk[1]); zp[4] += e1; n[1][k] = e1 * vk[1];
                float e2 = ex2f(wk[2] * vk[2]); zp[7] += e2; n[2][k] = e2 * vk[2];
                float e3 = ex2f(wk[3] * vk[3]); zp[9] += e3; n[3][k] = e3 * vk[3];
            }
            {   // symmetric off-diagonal pairs
                float e;
                e = ex2f(wk[0] * vk[1]); zp[1] += e; n[0][k] += e * vk[1]; n[1][k] += e * vk[0];
                e = ex2f(wk[0] * vk[2]); zp[2] += e; n[0][k] += e * vk[2]; n[2][k] += e * vk[0];
                e = ex2f(wk[0] * vk[3]); zp[3] += e; n[0][k] += e * vk[3]; n[3][k] += e * vk[0];
                e = ex2f(wk[1] * vk[2]); zp[5] += e; n[1][k] += e * vk[2]; n[2][k] += e * vk[1];
                e = ex2f(wk[1] * vk[3]); zp[6] += e; n[1][k] += e * vk[3]; n[3][k] += e * vk[1];
                e = ex2f(wk[2] * vk[3]); zp[8] += e; n[2][k] += e * vk[3]; n[3][k] += e * vk[2];
            }
        }

        // pairs: (0,0)=0 (0,1)=1 (0,2)=2 (0,3)=3 (1,1)=4 (1,2)=5 (1,3)=6 (2,2)=7 (2,3)=8 (3,3)=9
        szp[slice][0][px] = zp[0] + zp[1] + zp[2] + zp[3];
        szp[slice][1][px] = zp[1] + zp[4] + zp[5] + zp[6];
        szp[slice][2][px] = zp[2] + zp[5] + zp[7] + zp[8];
        szp[slice][3][px] = zp[3] + zp[6] + zp[8] + zp[9];
        __syncthreads();

        if (slice < 4) {
            float s = 0.0f;
            #pragma unroll
            for (int s8 = 0; s8 < 8; ++s8) s += szp[s8][slice][px];
            srz[slice][px] = rcpf(s);
        }
        __syncthreads();

        // coalesced stores: warp = fixed row, 32 consecutive px.
        // Plain st.global (NOT .cs): let the 126MB L2 absorb the write burst
        // and drain it between read bursts instead of contending eagerly.
        float* ob = out + ((size_t)b * 4 * C_ + slice * 8) * HW_ + p0 + px;
        #pragma unroll
        for (int i = 0; i < 4; ++i) {
            const float r = srz[i][px];
            #pragma unroll
            for (int k = 0; k < 8; ++k)
                ob[((size_t)i * C_ + k) * HW_] = n[i][k] * r;
        }
    };

    // ---- pipelined schedule: both prefetches up front ----
    prefetch(p0b, 0);
    prefetch(p0b + PX, 1);

    asm volatile("cp.async.wait_group 1;" ::: "memory");
    __syncthreads();
    process(p0b, 0);

    asm volatile("cp.async.wait_group 0;" ::: "memory");
    __syncthreads();   // orders tile0's srz reads before tile1 rewrites
    process(p0b + PX, 1);
}

extern "C" void kernel_launch(void* const* d_in, const int* in_sizes, int n_in,
                              void* d_out, int out_size)
{
    const float* frames = (const float*)d_in[0];
    float* out = (float*)d_out;
    frame_attn_kernel<<<B_ * (HW_ / PX) / NT, NTHR>>>(frames, out);   // 3200
}